// round 4
// baseline (speedup 1.0000x reference)
#include <cuda_runtime.h>
#include <cstdint>

// Persistent kernel, 3-deep TMA smem ring + deep L2 prefetch stream.
// L2 prefetch (no smem cost) runs 4 rows ahead; smem TMA loads then complete
// from L2 with ~250cyc latency instead of raw DRAM service time.

#define THREADS 512
#define MAXCHUNK 8   // N/4/THREADS = 16384/4/512
#define STAGES 3
#define PF_DIST 4    // L2 prefetch distance in rows (per-CTA stride G)

__global__ __launch_bounds__(THREADS, 1)
void sensory_persistent4(const float* __restrict__ enc,
                         const float* __restrict__ w,
                         const int*   __restrict__ pref,
                         float* __restrict__ out,
                         int B, int N, int F, int fmask)
{
    extern __shared__ __align__(128) unsigned char smem_dyn[];
    __shared__ __align__(8) unsigned long long mbar[STAGES];
    __shared__ float warpsums[THREADS / 32];

    const int tid = threadIdx.x;
    const unsigned rowbytes = (unsigned)F * 4u;

    uint32_t b_bar[STAGES], b_buf[STAGES];
    #pragma unroll
    for (int s = 0; s < STAGES; ++s) {
        b_bar[s] = (uint32_t)__cvta_generic_to_shared(&mbar[s]);
        b_buf[s] = (uint32_t)__cvta_generic_to_shared(smem_dyn + (size_t)s * rowbytes);
    }

    if (tid == 0) {
        #pragma unroll
        for (int s = 0; s < STAGES; ++s)
            asm volatile("mbarrier.init.shared::cta.b64 [%0], 1;" :: "r"(b_bar[s]) : "memory");
        asm volatile("fence.proxy.async.shared::cta;" ::: "memory");
    }
    __syncthreads();

    // ---- preload prefs (byte offsets) and weights into registers ----
    const int n4 = N >> 2;
    int4   poff[MAXCHUNK];
    float4 wv[MAXCHUNK];
    {
        const int4*   pref4 = (const int4*)pref;
        const float4* w4    = (const float4*)w;
        #pragma unroll
        for (int k = 0; k < MAXCHUNK; ++k) {
            int i4 = tid + k * THREADS;
            if (i4 < n4) {
                int4 p = pref4[i4];
                if (fmask) {
                    p.x = (p.x & fmask) << 2;
                    p.y = (p.y & fmask) << 2;
                    p.z = (p.z & fmask) << 2;
                    p.w = (p.w & fmask) << 2;
                } else {
                    p.x = (int)((unsigned)p.x % (unsigned)F) << 2;
                    p.y = (int)((unsigned)p.y % (unsigned)F) << 2;
                    p.z = (int)((unsigned)p.z % (unsigned)F) << 2;
                    p.w = (int)((unsigned)p.w % (unsigned)F) << 2;
                }
                poff[k] = p;
                wv[k]   = w4[i4];
            }
        }
    }

    const int G = gridDim.x;

    // ---- prologue: smem TMA for first two rows, L2 prefetch for rows +2,+3 ----
    if (tid == 0) {
        #pragma unroll
        for (int s = 0; s < 2; ++s) {
            int r = blockIdx.x + s * G;
            if (r < B) {
                asm volatile("mbarrier.arrive.expect_tx.shared::cta.b64 _, [%0], %1;"
                             :: "r"(b_bar[s]), "r"(rowbytes) : "memory");
                asm volatile("cp.async.bulk.shared::cta.global.mbarrier::complete_tx::bytes "
                             "[%0], [%1], %2, [%3];"
                             :: "r"(b_buf[s]), "l"(enc + (size_t)r * (size_t)F),
                                "r"(rowbytes), "r"(b_bar[s]) : "memory");
            }
        }
        #pragma unroll
        for (int s = 2; s < PF_DIST; ++s) {
            int r = blockIdx.x + s * G;
            if (r < B) {
                asm volatile("cp.async.bulk.prefetch.L2.global [%0], %1;"
                             :: "l"(enc + (size_t)r * (size_t)F), "r"(rowbytes) : "memory");
            }
        }
    }

    int cur = 0, nxt2 = 2;   // nxt2 = (cur + 2) % STAGES
    int par = 0;

    for (int r = blockIdx.x; r < B; r += G) {
        // ---- L2 prefetch PF_DIST rows ahead (no smem cost, deep DRAM queue) ----
        if (tid == 0) {
            const int rp = r + PF_DIST * G;
            if (rp < B) {
                asm volatile("cp.async.bulk.prefetch.L2.global [%0], %1;"
                             :: "l"(enc + (size_t)rp * (size_t)F), "r"(rowbytes) : "memory");
            }
        }

        // ---- wait for current buffer ----
        {
            const uint32_t mb = b_bar[cur];
            uint32_t done;
            asm volatile("{ .reg .pred p; "
                         "mbarrier.try_wait.parity.acquire.cta.shared::cta.b64 p, [%1], %2; "
                         "selp.b32 %0, 1, 0, p; }"
                         : "=r"(done) : "r"(mb), "r"((uint32_t)par) : "memory");
            if (!done) {
                asm volatile("{ .reg .pred P1; "
                             "WL%=: mbarrier.try_wait.parity.acquire.cta.shared::cta.b64 P1, [%0], %1, 0x989680; "
                             "@P1 bra.uni WD%=; bra.uni WL%=; WD%=: }"
                             :: "r"(mb), "r"((uint32_t)par) : "memory");
            }
        }

        const char* srow = (const char*)smem_dyn + (size_t)cur * rowbytes;

        // ---- gather into registers + local sum ----
        float lsum = 0.0f;
        float4 vals[MAXCHUNK];
        #pragma unroll
        for (int k = 0; k < MAXCHUNK; ++k) {
            int i4 = tid + k * THREADS;
            if (i4 < n4) {
                float4 v;
                v.x = *(const float*)(srow + poff[k].x) * wv[k].x;
                v.y = *(const float*)(srow + poff[k].y) * wv[k].y;
                v.z = *(const float*)(srow + poff[k].z) * wv[k].z;
                v.w = *(const float*)(srow + poff[k].w) * wv[k].w;
                vals[k] = v;
                lsum += (v.x + v.y) + (v.z + v.w);
            }
        }

        // ---- warp partial sums ----
        #pragma unroll
        for (int off = 16; off > 0; off >>= 1)
            lsum += __shfl_down_sync(0xFFFFFFFFu, lsum, off);
        if ((tid & 31) == 0) warpsums[tid >> 5] = lsum;
        __syncthreads();   // sums visible AND all reads of srow complete -> buffer free

        // ---- issue smem TMA for row r + 2G into the buffer freed above ----
        {
            const int r2 = r + 2 * G;
            if (r2 < B && tid == 0) {
                asm volatile("mbarrier.arrive.expect_tx.shared::cta.b64 _, [%0], %1;"
                             :: "r"(b_bar[nxt2]), "r"(rowbytes) : "memory");
                asm volatile("cp.async.bulk.shared::cta.global.mbarrier::complete_tx::bytes "
                             "[%0], [%1], %2, [%3];"
                             :: "r"(b_buf[nxt2]), "l"(enc + (size_t)r2 * (size_t)F),
                                "r"(rowbytes), "r"(b_bar[nxt2]) : "memory");
            }
        }

        // ---- redundant per-thread final reduce (no second barrier) ----
        float tot = 0.0f;
        #pragma unroll
        for (int ws = 0; ws < THREADS / 32; ++ws) tot += warpsums[ws];
        const float sub = (0.1f / (float)N) * tot;

        // ---- epilogue: subtract + relu, streaming float4 stores ----
        float4* out4 = (float4*)(out + (size_t)r * (size_t)N);
        #pragma unroll
        for (int k = 0; k < MAXCHUNK; ++k) {
            int i4 = tid + k * THREADS;
            if (i4 < n4) {
                float4 v = vals[k];
                float4 o;
                o.x = fmaxf(v.x - sub, 0.0f);
                o.y = fmaxf(v.y - sub, 0.0f);
                o.z = fmaxf(v.z - sub, 0.0f);
                o.w = fmaxf(v.w - sub, 0.0f);
                __stcs(out4 + i4, o);
            }
        }

        // advance ring
        cur  = (cur == STAGES - 1) ? 0 : cur + 1;
        nxt2 = (nxt2 == STAGES - 1) ? 0 : nxt2 + 1;
        if (cur == 0) par ^= 1;
    }
}

extern "C" void kernel_launch(void* const* d_in, const int* in_sizes, int n_in,
                              void* d_out, int out_size)
{
    const float* enc  = (const float*)d_in[0];
    const float* w    = (const float*)d_in[1];
    const int*   pref = (const int*)d_in[2];
    float*       out  = (float*)d_out;

    const int N = in_sizes[1];
    const int B = out_size / N;
    const int F = (int)((long long)in_sizes[0] / (long long)B);
    const int fmask = ((F & (F - 1)) == 0) ? (F - 1) : 0;

    int dev = 0;
    cudaGetDevice(&dev);
    int sms = 148;
    cudaDeviceGetAttribute(&sms, cudaDevAttrMultiProcessorCount, dev);
    int grid = (B < sms) ? B : sms;

    const int smem = STAGES * F * (int)sizeof(float);
    cudaFuncSetAttribute(sensory_persistent4,
                         cudaFuncAttributeMaxDynamicSharedMemorySize, smem);

    sensory_persistent4<<<grid, THREADS, smem>>>(enc, w, pref, out, B, N, F, fmask);
}

// round 5
// speedup vs baseline: 1.1787x; 1.1787x over previous
#include <cuda_runtime.h>
#include <cstdint>

// Persistent kernel, 3-deep TMA smem ring, 1024 threads (32 warps) for
// latency hiding. Pref byte-offsets packed 2x16-bit per register.
// No L2 prefetch (R4 showed it double-spends LTS bandwidth).

#define THREADS 1024
#define MAXCHUNK 4   // N/4/THREADS = 16384/4/1024
#define STAGES 3

__global__ __launch_bounds__(THREADS, 1)
void sensory_persistent5(const float* __restrict__ enc,
                         const float* __restrict__ w,
                         const int*   __restrict__ pref,
                         float* __restrict__ out,
                         int B, int N, int F, int fmask)
{
    extern __shared__ __align__(128) unsigned char smem_dyn[];
    __shared__ __align__(8) unsigned long long mbar[STAGES];
    __shared__ float warpsums[THREADS / 32];

    const int tid = threadIdx.x;
    const unsigned rowbytes = (unsigned)F * 4u;

    const uint32_t buf_base = (uint32_t)__cvta_generic_to_shared(smem_dyn);
    const uint32_t bar_base = (uint32_t)__cvta_generic_to_shared(&mbar[0]);

    if (tid == 0) {
        #pragma unroll
        for (int s = 0; s < STAGES; ++s)
            asm volatile("mbarrier.init.shared::cta.b64 [%0], 1;"
                         :: "r"(bar_base + 8u * s) : "memory");
        asm volatile("fence.proxy.async.shared::cta;" ::: "memory");
    }
    __syncthreads();

    // ---- preload prefs as packed 16-bit byte offsets + weights ----
    const int n4 = N >> 2;
    uint32_t plo[MAXCHUNK], phi[MAXCHUNK];   // (x | y<<16), (z | w<<16)
    float4 wv[MAXCHUNK];
    {
        const int4*   pref4 = (const int4*)pref;
        const float4* w4    = (const float4*)w;
        #pragma unroll
        for (int k = 0; k < MAXCHUNK; ++k) {
            int i4 = tid + k * THREADS;
            if (i4 < n4) {
                int4 p = pref4[i4];
                uint32_t ox, oy, oz, ow;
                if (fmask) {
                    ox = (uint32_t)(p.x & fmask) << 2;
                    oy = (uint32_t)(p.y & fmask) << 2;
                    oz = (uint32_t)(p.z & fmask) << 2;
                    ow = (uint32_t)(p.w & fmask) << 2;
                } else {
                    ox = ((unsigned)p.x % (unsigned)F) << 2;
                    oy = ((unsigned)p.y % (unsigned)F) << 2;
                    oz = ((unsigned)p.z % (unsigned)F) << 2;
                    ow = ((unsigned)p.w % (unsigned)F) << 2;
                }
                plo[k] = ox | (oy << 16);
                phi[k] = oz | (ow << 16);
                wv[k]  = w4[i4];
            } else {
                plo[k] = phi[k] = 0;
                wv[k] = make_float4(0.f, 0.f, 0.f, 0.f);
            }
        }
    }

    const int G = gridDim.x;

    // ---- prologue: TMA first two rows ----
    if (tid == 0) {
        #pragma unroll
        for (int s = 0; s < 2; ++s) {
            int r = blockIdx.x + s * G;
            if (r < B) {
                asm volatile("mbarrier.arrive.expect_tx.shared::cta.b64 _, [%0], %1;"
                             :: "r"(bar_base + 8u * s), "r"(rowbytes) : "memory");
                asm volatile("cp.async.bulk.shared::cta.global.mbarrier::complete_tx::bytes "
                             "[%0], [%1], %2, [%3];"
                             :: "r"(buf_base + s * rowbytes),
                                "l"(enc + (size_t)r * (size_t)F),
                                "r"(rowbytes), "r"(bar_base + 8u * s) : "memory");
            }
        }
    }

    int cur = 0, nxt2 = 2;   // nxt2 = (cur + 2) % STAGES
    int par = 0;

    for (int r = blockIdx.x; r < B; r += G) {
        // ---- wait for current buffer ----
        {
            const uint32_t mb = bar_base + 8u * cur;
            uint32_t done;
            asm volatile("{ .reg .pred p; "
                         "mbarrier.try_wait.parity.acquire.cta.shared::cta.b64 p, [%1], %2; "
                         "selp.b32 %0, 1, 0, p; }"
                         : "=r"(done) : "r"(mb), "r"((uint32_t)par) : "memory");
            if (!done) {
                asm volatile("{ .reg .pred P1; "
                             "WL%=: mbarrier.try_wait.parity.acquire.cta.shared::cta.b64 P1, [%0], %1, 0x989680; "
                             "@P1 bra.uni WD%=; bra.uni WL%=; WD%=: }"
                             :: "r"(mb), "r"((uint32_t)par) : "memory");
            }
        }

        const char* srow = (const char*)smem_dyn + (size_t)cur * rowbytes;

        // ---- gather into registers + local sum ----
        float lsum = 0.0f;
        float4 vals[MAXCHUNK];
        #pragma unroll
        for (int k = 0; k < MAXCHUNK; ++k) {
            float4 v;
            v.x = *(const float*)(srow + (plo[k] & 0xFFFFu)) * wv[k].x;
            v.y = *(const float*)(srow + (plo[k] >> 16))     * wv[k].y;
            v.z = *(const float*)(srow + (phi[k] & 0xFFFFu)) * wv[k].z;
            v.w = *(const float*)(srow + (phi[k] >> 16))     * wv[k].w;
            vals[k] = v;
            lsum += (v.x + v.y) + (v.z + v.w);
        }

        // ---- warp partial sums ----
        #pragma unroll
        for (int off = 16; off > 0; off >>= 1)
            lsum += __shfl_down_sync(0xFFFFFFFFu, lsum, off);
        if ((tid & 31) == 0) warpsums[tid >> 5] = lsum;
        __syncthreads();   // sums visible AND all reads of srow complete -> buffer free

        // ---- issue TMA for row r + 2G into the buffer freed above ----
        {
            const int r2 = r + 2 * G;
            if (r2 < B && tid == 0) {
                asm volatile("mbarrier.arrive.expect_tx.shared::cta.b64 _, [%0], %1;"
                             :: "r"(bar_base + 8u * nxt2), "r"(rowbytes) : "memory");
                asm volatile("cp.async.bulk.shared::cta.global.mbarrier::complete_tx::bytes "
                             "[%0], [%1], %2, [%3];"
                             :: "r"(buf_base + nxt2 * rowbytes),
                                "l"(enc + (size_t)r2 * (size_t)F),
                                "r"(rowbytes), "r"(bar_base + 8u * nxt2) : "memory");
            }
        }

        // ---- redundant per-thread final reduce (no second barrier) ----
        float tot = 0.0f;
        #pragma unroll
        for (int ws = 0; ws < THREADS / 32; ++ws) tot += warpsums[ws];
        const float sub = (0.1f / (float)N) * tot;

        // ---- epilogue: subtract + relu, streaming float4 stores ----
        float4* out4 = (float4*)(out + (size_t)r * (size_t)N);
        #pragma unroll
        for (int k = 0; k < MAXCHUNK; ++k) {
            int i4 = tid + k * THREADS;
            float4 v = vals[k];
            float4 o;
            o.x = fmaxf(v.x - sub, 0.0f);
            o.y = fmaxf(v.y - sub, 0.0f);
            o.z = fmaxf(v.z - sub, 0.0f);
            o.w = fmaxf(v.w - sub, 0.0f);
            __stcs(out4 + i4, o);
        }

        // advance ring
        cur  = (cur == STAGES - 1) ? 0 : cur + 1;
        nxt2 = (nxt2 == STAGES - 1) ? 0 : nxt2 + 1;
        if (cur == 0) par ^= 1;
    }
}

extern "C" void kernel_launch(void* const* d_in, const int* in_sizes, int n_in,
                              void* d_out, int out_size)
{
    const float* enc  = (const float*)d_in[0];
    const float* w    = (const float*)d_in[1];
    const int*   pref = (const int*)d_in[2];
    float*       out  = (float*)d_out;

    const int N = in_sizes[1];
    const int B = out_size / N;
    const int F = (int)((long long)in_sizes[0] / (long long)B);
    const int fmask = ((F & (F - 1)) == 0) ? (F - 1) : 0;

    int dev = 0;
    cudaGetDevice(&dev);
    int sms = 148;
    cudaDeviceGetAttribute(&sms, cudaDevAttrMultiProcessorCount, dev);
    int grid = (B < sms) ? B : sms;

    const int smem = STAGES * F * (int)sizeof(float);
    cudaFuncSetAttribute(sensory_persistent5,
                         cudaFuncAttributeMaxDynamicSharedMemorySize, smem);

    sensory_persistent5<<<grid, THREADS, smem>>>(enc, w, pref, out, B, N, F, fmask);
}

// round 6
// speedup vs baseline: 1.2934x; 1.0973x over previous
#include <cuda_runtime.h>
#include <cstdint>

// Persistent kernel, 3-deep TMA smem ring, 512 threads.
// R6: (a) refill TMA issued at TOP of iteration (buffer was released at the
// previous iteration's __syncthreads), (b) dynamic row scheduling via a
// global ticket counter (reset by a tiny kernel each launch) to absorb
// between-SM speed spread.

#define THREADS 512
#define MAXCHUNK 8   // N/4/THREADS = 16384/4/512
#define STAGES 3

__device__ unsigned g_ticket;

__global__ void reset_ticket_kernel() { g_ticket = 0u; }

__global__ __launch_bounds__(THREADS, 1)
void sensory_persistent6(const float* __restrict__ enc,
                         const float* __restrict__ w,
                         const int*   __restrict__ pref,
                         float* __restrict__ out,
                         int B, int N, int F, int fmask)
{
    extern __shared__ __align__(128) unsigned char smem_dyn[];
    __shared__ __align__(8) unsigned long long mbar[STAGES];
    __shared__ float warpsums[THREADS / 32];
    __shared__ int rowids_sm[STAGES];

    const int tid = threadIdx.x;
    const unsigned rowbytes = (unsigned)F * 4u;

    uint32_t b_bar[STAGES], b_buf[STAGES];
    #pragma unroll
    for (int s = 0; s < STAGES; ++s) {
        b_bar[s] = (uint32_t)__cvta_generic_to_shared(&mbar[s]);
        b_buf[s] = (uint32_t)__cvta_generic_to_shared(smem_dyn + (size_t)s * rowbytes);
    }

    if (tid == 0) {
        #pragma unroll
        for (int s = 0; s < STAGES; ++s)
            asm volatile("mbarrier.init.shared::cta.b64 [%0], 1;" :: "r"(b_bar[s]) : "memory");
        asm volatile("fence.proxy.async.shared::cta;" ::: "memory");
    }
    __syncthreads();

    // ---- preload prefs (byte offsets) and weights into registers ----
    const int n4 = N >> 2;
    int4   poff[MAXCHUNK];
    float4 wv[MAXCHUNK];
    {
        const int4*   pref4 = (const int4*)pref;
        const float4* w4    = (const float4*)w;
        #pragma unroll
        for (int k = 0; k < MAXCHUNK; ++k) {
            int i4 = tid + k * THREADS;
            if (i4 < n4) {
                int4 p = pref4[i4];
                if (fmask) {
                    p.x = (p.x & fmask) << 2;
                    p.y = (p.y & fmask) << 2;
                    p.z = (p.z & fmask) << 2;
                    p.w = (p.w & fmask) << 2;
                } else {
                    p.x = (int)((unsigned)p.x % (unsigned)F) << 2;
                    p.y = (int)((unsigned)p.y % (unsigned)F) << 2;
                    p.z = (int)((unsigned)p.z % (unsigned)F) << 2;
                    p.w = (int)((unsigned)p.w % (unsigned)F) << 2;
                }
                poff[k] = p;
                wv[k]   = w4[i4];
            }
        }
    }

    // ---- prologue: claim and issue first two rows ----
    if (tid == 0) {
        #pragma unroll
        for (int s = 0; s < 2; ++s) {
            int r = (int)atomicAdd(&g_ticket, 1u);
            rowids_sm[s] = r;
            if (r < B) {
                asm volatile("mbarrier.arrive.expect_tx.shared::cta.b64 _, [%0], %1;"
                             :: "r"(b_bar[s]), "r"(rowbytes) : "memory");
                asm volatile("cp.async.bulk.shared::cta.global.mbarrier::complete_tx::bytes "
                             "[%0], [%1], %2, [%3];"
                             :: "r"(b_buf[s]), "l"(enc + (size_t)r * (size_t)F),
                                "r"(rowbytes), "r"(b_bar[s]) : "memory");
            }
        }
    }
    __syncthreads();

    int cur = 0, nxt2 = 2;   // nxt2 = (cur + 2) % STAGES
    int par = 0;

    for (;;) {
        const int r = rowids_sm[cur];   // claimed 2 iterations ago (or prologue)
        if (r >= B) break;

        // ---- claim + issue refill TMA at TOP of iteration.
        // Buffer nxt2 was fully consumed before the PREVIOUS iteration's
        // __syncthreads, so it is free now; issuing here gives the TMA a
        // full iteration of head start versus issuing after the barrier.
        if (tid == 0) {
            int r2 = (int)atomicAdd(&g_ticket, 1u);
            rowids_sm[nxt2] = r2;
            if (r2 < B) {
                asm volatile("mbarrier.arrive.expect_tx.shared::cta.b64 _, [%0], %1;"
                             :: "r"(b_bar[nxt2]), "r"(rowbytes) : "memory");
                asm volatile("cp.async.bulk.shared::cta.global.mbarrier::complete_tx::bytes "
                             "[%0], [%1], %2, [%3];"
                             :: "r"(b_buf[nxt2]), "l"(enc + (size_t)r2 * (size_t)F),
                                "r"(rowbytes), "r"(b_bar[nxt2]) : "memory");
            }
        }

        // ---- wait for current buffer ----
        {
            const uint32_t mb = b_bar[cur];
            uint32_t done;
            asm volatile("{ .reg .pred p; "
                         "mbarrier.try_wait.parity.acquire.cta.shared::cta.b64 p, [%1], %2; "
                         "selp.b32 %0, 1, 0, p; }"
                         : "=r"(done) : "r"(mb), "r"((uint32_t)par) : "memory");
            if (!done) {
                asm volatile("{ .reg .pred P1; "
                             "WL%=: mbarrier.try_wait.parity.acquire.cta.shared::cta.b64 P1, [%0], %1, 0x989680; "
                             "@P1 bra.uni WD%=; bra.uni WL%=; WD%=: }"
                             :: "r"(mb), "r"((uint32_t)par) : "memory");
            }
        }

        const char* srow = (const char*)smem_dyn + (size_t)cur * rowbytes;

        // ---- gather into registers + local sum ----
        float lsum = 0.0f;
        float4 vals[MAXCHUNK];
        #pragma unroll
        for (int k = 0; k < MAXCHUNK; ++k) {
            float4 v;
            v.x = *(const float*)(srow + poff[k].x) * wv[k].x;
            v.y = *(const float*)(srow + poff[k].y) * wv[k].y;
            v.z = *(const float*)(srow + poff[k].z) * wv[k].z;
            v.w = *(const float*)(srow + poff[k].w) * wv[k].w;
            vals[k] = v;
            lsum += (v.x + v.y) + (v.z + v.w);
        }

        // ---- warp partial sums ----
        #pragma unroll
        for (int off = 16; off > 0; off >>= 1)
            lsum += __shfl_down_sync(0xFFFFFFFFu, lsum, off);
        if ((tid & 31) == 0) warpsums[tid >> 5] = lsum;
        __syncthreads();   // sums visible AND all reads of srow complete -> buffer release point

        // ---- redundant per-thread final reduce (no second barrier) ----
        float tot = 0.0f;
        #pragma unroll
        for (int ws = 0; ws < THREADS / 32; ++ws) tot += warpsums[ws];
        const float sub = (0.1f / (float)N) * tot;

        // ---- epilogue: subtract + relu, streaming float4 stores ----
        float4* out4 = (float4*)(out + (size_t)r * (size_t)N);
        #pragma unroll
        for (int k = 0; k < MAXCHUNK; ++k) {
            int i4 = tid + k * THREADS;
            float4 v = vals[k];
            float4 o;
            o.x = fmaxf(v.x - sub, 0.0f);
            o.y = fmaxf(v.y - sub, 0.0f);
            o.z = fmaxf(v.z - sub, 0.0f);
            o.w = fmaxf(v.w - sub, 0.0f);
            __stcs(out4 + i4, o);
        }

        // advance ring
        cur  = (cur == STAGES - 1) ? 0 : cur + 1;
        nxt2 = (nxt2 == STAGES - 1) ? 0 : nxt2 + 1;
        if (cur == 0) par ^= 1;
    }
}

extern "C" void kernel_launch(void* const* d_in, const int* in_sizes, int n_in,
                              void* d_out, int out_size)
{
    const float* enc  = (const float*)d_in[0];
    const float* w    = (const float*)d_in[1];
    const int*   pref = (const int*)d_in[2];
    float*       out  = (float*)d_out;

    const int N = in_sizes[1];
    const int B = out_size / N;
    const int F = (int)((long long)in_sizes[0] / (long long)B);
    const int fmask = ((F & (F - 1)) == 0) ? (F - 1) : 0;

    int dev = 0;
    cudaGetDevice(&dev);
    int sms = 148;
    cudaDeviceGetAttribute(&sms, cudaDevAttrMultiProcessorCount, dev);
    int grid = (B < sms) ? B : sms;

    const int smem = STAGES * F * (int)sizeof(float);
    cudaFuncSetAttribute(sensory_persistent6,
                         cudaFuncAttributeMaxDynamicSharedMemorySize, smem);

    reset_ticket_kernel<<<1, 1>>>();
    sensory_persistent6<<<grid, THREADS, smem>>>(enc, w, pref, out, B, N, F, fmask);
}